// round 14
// baseline (speedup 1.0000x reference)
#include <cuda_runtime.h>
#include <cuda_bf16.h>

#define BTn 3200
#define Vn 25
#define Dn 128
#define NEn 1024
#define NQn 4
#define NVn (BTn*Vn)          // 80000
#define ALPHAc 0.1f
#define BETA1 1.25f
#define SLOPEc 0.2f
#define LNEPSc 1e-5f
#define MARGIN_I 263          // ceil(4e-3 * 65536): integer-domain margin

// Scratch (allocation-free rule: __device__ globals)
__device__ float g_res[NVn*Dn];
__device__ float g_ref[NVn*Dn];
__device__ float g_xnorm[NVn];
__device__ float g_cnorm[NQn*NEn];
__device__ float g_lossv[NQn*NVn];
__device__ __nv_bfloat16 g_wh[NQn*NEn*Dn];   // codebook hi bf16
__device__ __nv_bfloat16 g_wl[NQn*NEn*Dn];   // codebook lo bf16 (w - hi)
__device__ int g_cand[NVn*16];
__device__ int g_ccnt[NVn];
__device__ int g_chosen[NVn];

__device__ __forceinline__ unsigned smem_u32(const void* p) {
    unsigned a;
    asm("{ .reg .u64 t; cvta.to.shared.u64 t, %1; cvt.u32.u64 %0, t; }"
        : "=r"(a) : "l"(p));
    return a;
}
__device__ __forceinline__ void ldmx4(unsigned* r, unsigned addr) {
    asm volatile("ldmatrix.sync.aligned.m8n8.x4.shared.b16 {%0,%1,%2,%3}, [%4];"
        : "=r"(r[0]), "=r"(r[1]), "=r"(r[2]), "=r"(r[3]) : "r"(addr));
}
__device__ __forceinline__ void mma16816(float* c, const unsigned* a, const unsigned* b) {
    asm volatile("mma.sync.aligned.m16n8k16.row.col.f32.bf16.bf16.f32 "
        "{%0,%1,%2,%3}, {%4,%5,%6,%7}, {%8,%9}, {%0,%1,%2,%3};"
        : "+f"(c[0]), "+f"(c[1]), "+f"(c[2]), "+f"(c[3])
        : "r"(a[0]), "r"(a[1]), "r"(a[2]), "r"(a[3]), "r"(b[0]), "r"(b[1]));
}
// branch-free sorted top-2 insert over u32 keys (3-op IMNMX network)
__device__ __forceinline__ void ins2u(unsigned* tt, unsigned kk) {
    unsigned t1 = min(tt[1], kk);
    unsigned a0 = min(tt[0], t1), b1 = max(tt[0], t1);
    tt[0] = a0; tt[1] = b1;
}
// quantized int key from scaled distance float (floor = monotone)
__device__ __forceinline__ unsigned mkkey(float kf, int code) {
    int ik;
    asm("cvt.rmi.s32.f32 %0, %1;" : "=r"(ik) : "f"(kf));
    return ((unsigned)(ik + (1 << 21)) << 10) | (unsigned)code;
}

// smem layout for k_pref (bytes). MRG aliases the W tiles (dead after mainloop)
// so total fits 2 CTAs/SM (108544 * 2 = 217088 <= 227KB carveout).
#define RSb 272                       // row stride = 136 halves
#define SM_CN   0
#define SM_XH   4096
#define SM_XL   (4096 + 34816)
#define SM_WH   (4096 + 69632)
#define SM_WL   (4096 + 69632 + 17408)
#define SM_MRG  SM_WH
#define PF_SMEM (SM_WH + 34816)      // 108544

// smem float offsets for k_gcn (4 n-rows per 512-thread block)
#define GA   0
#define GW   640
#define GPN  17536                    // per-n base
#define GPN_STRIDE 9764               // sres 3200 + snsm 3300 + sln 3200 + mu 32 + sd 32
#define GCN_FLOATS (GPN + 4*GPN_STRIDE)   // 56592 floats = 226368 B

// ================================================================ setup
__global__ void k_wconv(const float* __restrict__ emb) {
    int i = blockIdx.x*blockDim.x + threadIdx.x;
    if (i < NQn*NEn*Dn) {
        float x = emb[i];
        __nv_bfloat16 h = __float2bfloat16(x);
        g_wh[i] = h;
        g_wl[i] = __float2bfloat16(__fadd_rn(x, -__bfloat162float(h)));
    }
}
__global__ void k_cnorm(const float* __restrict__ emb) {
    int r = blockIdx.x*(blockDim.x>>5) + (threadIdx.x>>5);
    int lane = threadIdx.x & 31;
    if (r < NQn*NEn) {
        const float* w = emb + (size_t)r*Dn;
        float s = 0.f;
        #pragma unroll
        for (int j = 0; j < 4; j++) { float v = w[lane + 32*j]; s = __fadd_rn(s, __fmul_rn(v, v)); }
        #pragma unroll
        for (int o = 16; o; o >>= 1) s = __fadd_rn(s, __shfl_down_sync(0xffffffffu, s, o));
        if (lane == 0) g_cnorm[r] = s;
    }
}

// ---------------- GCN refine (bit-exact) + fused xnorm; 4 n-rows per block
__global__ __launch_bounds__(512) void k_gcn(const float* __restrict__ A,
        const float* __restrict__ W, const float* __restrict__ bb,
        const float* __restrict__ lns, const float* __restrict__ lnb,
        const float* __restrict__ z, int stage) {
    extern __shared__ float sm[];
    float* sA = sm + GA;
    float* sW = sm + GW;
    int t = threadIdx.x;
    int nn = t >> 7;            // 0..3: which n-row this 128-thread group owns
    int d  = t & 127;
    float* base = sm + GPN + nn*GPN_STRIDE;
    float* sres = base;
    float* snsm = base + 3200;
    float* sln  = base + 6500;
    float* smu  = base + 9700;
    float* ssd  = base + 9732;
    int n = blockIdx.x*4 + nn;
    const float* resg = (stage == 0 ? z : g_res) + (size_t)n*(Vn*Dn);

    for (int i = t; i < Vn*Vn; i += 512) sA[i] = A[i];
    for (int i = t; i < Dn*Dn; i += 512) sW[(i>>7)*132 + (i&127)] = W[i];
    #pragma unroll
    for (int v = 0; v < Vn; v++) sres[v*Dn+d] = resg[v*Dn+d];
    __syncthreads();

    // neigh = A @ res  (k ascending fma chain, SGEMM order)
    {
        float acc[Vn];
        #pragma unroll
        for (int v = 0; v < Vn; v++) acc[v] = 0.f;
        for (int w = 0; w < Vn; w++) {
            float rv = sres[w*Dn+d];
            #pragma unroll
            for (int v = 0; v < Vn; v++) acc[v] = fmaf(sA[v*Vn+w], rv, acc[v]);
        }
        #pragma unroll
        for (int v = 0; v < Vn; v++) snsm[v*132+d] = acc[v];
    }
    __syncthreads();

    // linear (neigh @ W^T) + bias + LeakyReLU ; k ascending fma chain
    {
        float acc[Vn];
        #pragma unroll
        for (int v = 0; v < Vn; v++) acc[v] = 0.f;
        for (int kk = 0; kk < Dn; kk += 4) {
            float4 w4 = *reinterpret_cast<const float4*>(&sW[d*132+kk]);
            #pragma unroll
            for (int v = 0; v < Vn; v++) {
                float4 x4 = *reinterpret_cast<const float4*>(&snsm[v*132+kk]);
                float a = acc[v];
                a = fmaf(x4.x, w4.x, a); a = fmaf(x4.y, w4.y, a);
                a = fmaf(x4.z, w4.z, a); a = fmaf(x4.w, w4.w, a);
                acc[v] = a;
            }
        }
        float bd = bb[d];
        #pragma unroll
        for (int v = 0; v < Vn; v++) {
            float val = __fadd_rn(acc[v], bd);
            val = (val >= 0.f) ? val : __fmul_rn(SLOPEc, val);
            sln[v*Dn+d] = val;
        }
    }
    __syncthreads();

    // LayerNorm stats: warp-per-row within n-group (XLA reduce order)
    {
        int warp = (t >> 5) & 3, lane = t & 31;
        for (int v = warp; v < Vn; v += 4) {
            float s = 0.f;
            #pragma unroll
            for (int j = 0; j < 4; j++) s = __fadd_rn(s, sln[v*Dn + lane + 32*j]);
            #pragma unroll
            for (int o = 16; o; o >>= 1) s = __fadd_rn(s, __shfl_down_sync(0xffffffffu, s, o));
            float mu = __shfl_sync(0xffffffffu, s, 0) * (1.f/Dn);
            float s2 = 0.f;
            #pragma unroll
            for (int j = 0; j < 4; j++) {
                float tt = __fadd_rn(sln[v*Dn + lane + 32*j], -mu);
                s2 = __fadd_rn(s2, __fmul_rn(tt, tt));
            }
            #pragma unroll
            for (int o = 16; o; o >>= 1) s2 = __fadd_rn(s2, __shfl_down_sync(0xffffffffu, s2, o));
            if (lane == 0) { smu[v] = mu; ssd[v] = __fsqrt_rn(__fadd_rn(s2*(1.f/Dn), LNEPSc)); }
        }
    }
    __syncthreads();

    // apply LN + residual add; stash refined^2 into snsm (dead buffer) for xnorm
    {
        float scl = lns[d], bia = lnb[d];
        float* refg = g_ref + (size_t)n*(Vn*Dn);
        #pragma unroll
        for (int v = 0; v < Vn; v++) {
            float a = __fadd_rn(sln[v*Dn+d], -smu[v]);
            float normed = __fadd_rn(__fmul_rn(__fdiv_rn(a, ssd[v]), scl), bia);
            float r = __fadd_rn(sres[v*Dn+d], __fmul_rn(ALPHAc, normed));
            refg[v*Dn+d] = r;
            snsm[v*132+d] = __fmul_rn(r, r);
        }
    }
    __syncthreads();

    // fused xnorm: identical order to standalone (serial j-chain + shfl tree)
    {
        int warp = (t >> 5) & 3, lane = t & 31;
        for (int v = warp; v < Vn; v += 4) {
            float s = 0.f;
            #pragma unroll
            for (int j = 0; j < 4; j++) s = __fadd_rn(s, snsm[v*132 + lane + 32*j]);
            #pragma unroll
            for (int o = 16; o; o >>= 1) s = __fadd_rn(s, __shfl_down_sync(0xffffffffu, s, o));
            if (lane == 0) g_xnorm[n*Vn + v] = s;
        }
    }
}

// ---------------- HMMA prefilter: u32 keys, top-2/lane (IMNMX), uint4 W loads
__global__ __launch_bounds__(256, 2) void k_pref(int stage) {
    extern __shared__ char smc[];
    float* scn = reinterpret_cast<float*>(smc + SM_CN);
    int t = threadIdx.x, wid = t >> 5, lane = t & 31;
    int qbase = blockIdx.x * 128;

    // premultiplied code norms: cn * 2^16 (integer-key domain)
    for (int i = t; i < NEn; i += 256) scn[i] = g_cnorm[stage*NEn + i] * 65536.f;
    // X -> bf16 hi/lo in smem, row stride 136 halves
    for (int i = t; i < 128*Dn; i += 256) {
        int q = i >> 7, k = i & 127;
        float x = g_ref[(size_t)(qbase + q)*Dn + k];
        __nv_bfloat16 h = __float2bfloat16(x);
        __nv_bfloat16 l = __float2bfloat16(__fadd_rn(x, -__bfloat162float(h)));
        *reinterpret_cast<__nv_bfloat16*>(smc + SM_XH + q*RSb + k*2) = h;
        *reinterpret_cast<__nv_bfloat16*>(smc + SM_XL + q*RSb + k*2) = l;
    }

    int q0 = wid * 16;
    unsigned xbh = smem_u32(smc + SM_XH), xbl = smem_u32(smc + SM_XL);
    unsigned wbh = smem_u32(smc + SM_WH), wbl = smem_u32(smc + SM_WL);
    int g = lane >> 3, ri = lane & 7;
    unsigned a_off = (unsigned)((q0 + ri + (g & 1)*8)*RSb + (g >> 1)*16);
    unsigned b_roff = (unsigned)((ri + (g >> 1)*8)*RSb + (g & 1)*16);

    unsigned tlo[2], thi[2];
    tlo[0] = tlo[1] = 0xFFFFFFFFu;
    thi[0] = thi[1] = 0xFFFFFFFFu;

    const unsigned* whp = reinterpret_cast<const unsigned*>(g_wh) + (size_t)stage*65536;
    const unsigned* wlp = reinterpret_cast<const unsigned*>(g_wl) + (size_t)stage*65536;

    for (int chunk = 0; chunk < 16; chunk++) {
        __syncthreads();
        {   // vectorized W tile load: 64 rows x 16 uint4 per array
            const uint4* wh4 = reinterpret_cast<const uint4*>(whp + chunk*4096);
            const uint4* wl4 = reinterpret_cast<const uint4*>(wlp + chunk*4096);
            for (int i = t; i < 64*16; i += 256) {
                int r = i >> 4, c = i & 15;
                *reinterpret_cast<uint4*>(smc + SM_WH + r*RSb + c*16) = wh4[i];
                *reinterpret_cast<uint4*>(smc + SM_WL + r*RSb + c*16) = wl4[i];
            }
        }
        __syncthreads();

        float acc[8][4];
        #pragma unroll
        for (int n = 0; n < 8; n++)
            #pragma unroll
            for (int j = 0; j < 4; j++) acc[n][j] = 0.f;

        #pragma unroll
        for (int kt = 0; kt < 8; kt++) {
            unsigned ah[4], al[4];
            ldmx4(ah, xbh + a_off + kt*32);
            ldmx4(al, xbl + a_off + kt*32);
            #pragma unroll
            for (int np = 0; np < 4; np++) {
                unsigned bh[4], bl[4];
                unsigned bo = (unsigned)(np*16*RSb) + b_roff + kt*32;
                ldmx4(bh, wbh + bo);
                ldmx4(bl, wbl + bo);
                mma16816(acc[np*2],   ah, &bh[0]);
                mma16816(acc[np*2],   ah, &bl[0]);
                mma16816(acc[np*2],   al, &bh[0]);
                mma16816(acc[np*2+1], ah, &bh[2]);
                mma16816(acc[np*2+1], ah, &bl[2]);
                mma16816(acc[np*2+1], al, &bh[2]);
            }
        }
        // epilogue: key = floor(2^16*(cn - 2*acc)) biased, code in low 10 bits
        int cb0 = chunk*64 + (lane & 3)*2;
        #pragma unroll
        for (int nt = 0; nt < 8; nt++) {
            int c0 = cb0 + nt*8;
            float cn0 = scn[c0], cn1 = scn[c0 + 1];
            ins2u(tlo, mkkey(fmaf(-131072.f, acc[nt][0], cn0), c0));
            ins2u(tlo, mkkey(fmaf(-131072.f, acc[nt][1], cn1), c0 + 1));
            ins2u(thi, mkkey(fmaf(-131072.f, acc[nt][2], cn0), c0));
            ins2u(thi, mkkey(fmaf(-131072.f, acc[nt][3], cn1), c0 + 1));
        }
    }

    // merge phase: W tiles are dead; MRG aliases them (barrier orders reuse)
    __syncthreads();
    unsigned* mrg = reinterpret_cast<unsigned*>(smc + SM_MRG);
    {
        int ql = q0 + (lane >> 2), slot = lane & 3;
        mrg[(ql*4 + slot)*2    ] = tlo[0];
        mrg[(ql*4 + slot)*2 + 1] = tlo[1];
        int qh = q0 + 8 + (lane >> 2);
        mrg[(qh*4 + slot)*2    ] = thi[0];
        mrg[(qh*4 + slot)*2 + 1] = thi[1];
    }
    __syncthreads();
    if (t < 128) {
        const unsigned* e = &mrg[t*8];
        unsigned best = 0xFFFFFFFFu;
        #pragma unroll
        for (int j = 0; j < 8; j++) best = min(best, e[j]);
        unsigned thr = (best >> 10) + MARGIN_I;
        bool fb = false;
        #pragma unroll
        for (int s = 0; s < 4; s++) if ((e[s*2 + 1] >> 10) <= thr) fb = true;
        int gq = qbase + t, cnt = 0;
        if (fb) {
            g_ccnt[gq] = 255;
        } else {
            #pragma unroll
            for (int j = 0; j < 8; j++) {
                if ((e[j] >> 10) <= thr) {
                    g_cand[(size_t)gq*16 + cnt] = (int)(e[j] & 0x3FFu);
                    cnt++;
                }
            }
            g_ccnt[gq] = cnt;
            if (cnt == 1) g_chosen[gq] = (int)(best & 0x3FFu);
        }
    }
}

// ---------------- exact rescore: thread-per-query fast path; ballot loop for slow
__global__ __launch_bounds__(256) void k_rescore(const float* __restrict__ emb, int stage) {
    int t = threadIdx.x, lane = t & 31;
    int q = blockIdx.x*256 + t;
    int cnt = (q < NVn) ? g_ccnt[q] : 1;
    unsigned slow = __ballot_sync(0xffffffffu, cnt != 1);
    if (!slow) return;
    const float* cb = emb + (size_t)stage*(NEn*Dn);
    const float* cng = g_cnorm + stage*NEn;
    while (slow) {
        int src = __ffs(slow) - 1;
        slow &= slow - 1;
        int sq   = __shfl_sync(0xffffffffu, q, src);
        int scnt = __shfl_sync(0xffffffffu, cnt, src);
        const float* x = g_ref + (size_t)sq*Dn;
        float xn = g_xnorm[sq];
        float bd = 3.4028235e38f; int bi = 0x7fffffff;
        if (scnt <= 16) {
            if (lane < scnt) {
                int c = g_cand[(size_t)sq*16 + lane];
                const float* w = cb + (size_t)c*Dn;
                float acc = 0.f;
                for (int k = 0; k < Dn; k++) acc = fmaf(x[k], w[k], acc);
                bd = __fadd_rn(__fadd_rn(xn, -2.f*acc), cng[c]);
                bi = c;
            }
        } else {
            for (int c = lane; c < NEn; c += 32) {
                const float* w = cb + (size_t)c*Dn;
                float acc = 0.f;
                for (int k = 0; k < Dn; k++) acc = fmaf(x[k], w[k], acc);
                float d = __fadd_rn(__fadd_rn(xn, -2.f*acc), cng[c]);
                if (d < bd) { bd = d; bi = c; }
            }
        }
        #pragma unroll
        for (int o = 16; o; o >>= 1) {
            float od = __shfl_down_sync(0xffffffffu, bd, o);
            int   oi = __shfl_down_sync(0xffffffffu, bi, o);
            if (od < bd || (od == bd && oi < bi)) { bd = od; bi = oi; }
        }
        if (lane == 0) g_chosen[sq] = bi;
    }
}

// ---------------- update (bit-exact): stage0 reads z / writes q; stage3 fused fixup
__global__ __launch_bounds__(256) void k_update(const float* __restrict__ emb, int stage,
        const float* __restrict__ z, float* __restrict__ zq, float* __restrict__ oidx) {
    int t = threadIdx.x;
    int base = blockIdx.x * 64;
    const float* cb = emb + (size_t)stage*(NEn*Dn);
    int v = t >> 2;
    int dseg = t & 3;
    int gvec = base + v;
    int idx = g_chosen[gvec];
    const float* q = cb + (size_t)idx*Dn;
    const float* rsrc = (stage == 0 ? z : g_res) + (size_t)gvec*Dn;
    float* resp = g_res + (size_t)gvec*Dn;
    float* zqp  = zq + (size_t)gvec*Dn;
    const float* zp = z + (size_t)gvec*Dn;
    float ls = 0.f;
    #pragma unroll
    for (int j = 0; j < 8; j++) {
        int dd = dseg*32 + j*4;
        float4 qv = *reinterpret_cast<const float4*>(&q[dd]);
        float4 rv = *reinterpret_cast<const float4*>(&rsrc[dd]);
        float dx = __fadd_rn(qv.x, -rv.x), dy = __fadd_rn(qv.y, -rv.y);
        float dz = __fadd_rn(qv.z, -rv.z), dw = __fadd_rn(qv.w, -rv.w);
        ls = __fadd_rn(ls, __fmul_rn(dx,dx));
        ls = __fadd_rn(ls, __fmul_rn(dy,dy));
        ls = __fadd_rn(ls, __fmul_rn(dz,dz));
        ls = __fadd_rn(ls, __fmul_rn(dw,dw));
        float4 nr = make_float4(__fadd_rn(rv.x,-qv.x), __fadd_rn(rv.y,-qv.y),
                                __fadd_rn(rv.z,-qv.z), __fadd_rn(rv.w,-qv.w));
        *reinterpret_cast<float4*>(&resp[dd]) = nr;
        float4 nz;
        if (stage == 0) {
            nz = qv;                           // 0 + q == q exactly
        } else {
            float4 zv = *reinterpret_cast<const float4*>(&zqp[dd]);
            nz = make_float4(__fadd_rn(zv.x,qv.x), __fadd_rn(zv.y,qv.y),
                             __fadd_rn(zv.z,qv.z), __fadd_rn(zv.w,qv.w));
        }
        if (stage == 3) {                      // straight-through: z + (cum - z)
            float4 zz = *reinterpret_cast<const float4*>(&zp[dd]);
            nz = make_float4(__fadd_rn(zz.x, __fadd_rn(nz.x, -zz.x)),
                             __fadd_rn(zz.y, __fadd_rn(nz.y, -zz.y)),
                             __fadd_rn(zz.z, __fadd_rn(nz.z, -zz.z)),
                             __fadd_rn(zz.w, __fadd_rn(nz.w, -zz.w)));
        }
        *reinterpret_cast<float4*>(&zqp[dd]) = nz;
    }
    #pragma unroll
    for (int o = 2; o; o >>= 1) ls = __fadd_rn(ls, __shfl_down_sync(0xffffffffu, ls, o, 4));
    if (dseg == 0) g_lossv[stage*NVn + gvec] = __fmul_rn(BETA1, ls*(1.f/Dn));
    if (dseg == 1) oidx[(size_t)gvec*NQn + stage] = (float)idx;
}

__global__ void k_loss(float* __restrict__ out) {
    __shared__ float red[1024];
    int t = threadIdx.x;
    float s = 0.f;
    const float4* p = reinterpret_cast<const float4*>(g_lossv);
    for (int i = t; i < (NQn*NVn)/4; i += 1024) {
        float4 v = p[i];
        s = __fadd_rn(s, v.x); s = __fadd_rn(s, v.y);
        s = __fadd_rn(s, v.z); s = __fadd_rn(s, v.w);
    }
    red[t] = s; __syncthreads();
    for (int o = 512; o; o >>= 1) {
        if (t < o) red[t] = __fadd_rn(red[t], red[t+o]);
        __syncthreads();
    }
    if (t == 0) out[0] = red[0] * (1.f/(float)(NQn*NVn));
}

extern "C" void kernel_launch(void* const* d_in, const int* in_sizes, int n_in,
                              void* d_out, int out_size) {
    const float* z   = (const float*)d_in[0];
    const float* emb = (const float*)d_in[1];
    const float* A   = (const float*)d_in[2];
    const float* W   = (const float*)d_in[3];
    const float* b   = (const float*)d_in[4];
    const float* lns = (const float*)d_in[5];
    const float* lnb = (const float*)d_in[6];
    float* out  = (float*)d_out;
    float* zq   = out;
    float* loss = out + (size_t)NVn*Dn;
    float* oidx = loss + 1;

    const int GCN_SMEM = GCN_FLOATS * 4;   // 226368 B
    cudaFuncSetAttribute(k_gcn,  cudaFuncAttributeMaxDynamicSharedMemorySize, GCN_SMEM);
    cudaFuncSetAttribute(k_pref, cudaFuncAttributeMaxDynamicSharedMemorySize, PF_SMEM);

    k_cnorm<<<512, 256>>>(emb);
    k_wconv<<<2048, 256>>>(emb);
    for (int k = 0; k < NQn; k++) {
        k_gcn<<<BTn/4, 512, GCN_SMEM>>>(A, W, b, lns, lnb, z, k);
        k_pref<<<625, 256, PF_SMEM>>>(k);
        k_rescore<<<313, 256>>>(emb, k);
        k_update<<<1250, 256>>>(emb, k, z, zq, oidx);
    }
    k_loss<<<1, 1024>>>(loss);
}

// round 15
// speedup vs baseline: 2.3560x; 2.3560x over previous
#include <cuda_runtime.h>
#include <cuda_bf16.h>

#define BTn 3200
#define Vn 25
#define Dn 128
#define NEn 1024
#define NQn 4
#define NVn (BTn*Vn)          // 80000
#define ALPHAc 0.1f
#define BETA1 1.25f
#define SLOPEc 0.2f
#define LNEPSc 1e-5f
#define MARGIN_I 263          // ceil(4e-3 * 65536): integer-domain margin

// Scratch (allocation-free rule: __device__ globals)
__device__ float g_res[NVn*Dn];
__device__ float g_ref[NVn*Dn];
__device__ float g_xnorm[NVn];
__device__ float g_cnorm[NQn*NEn];
__device__ float g_lossv[NQn*NVn];
__device__ __nv_bfloat16 g_wh[NQn*NEn*Dn];   // codebook hi bf16
__device__ __nv_bfloat16 g_wl[NQn*NEn*Dn];   // codebook lo bf16 (w - hi)
__device__ int g_cand[NVn*16];
__device__ int g_ccnt[NVn];
__device__ int g_chosen[NVn];

__device__ __forceinline__ unsigned smem_u32(const void* p) {
    unsigned a;
    asm("{ .reg .u64 t; cvta.to.shared.u64 t, %1; cvt.u32.u64 %0, t; }"
        : "=r"(a) : "l"(p));
    return a;
}
__device__ __forceinline__ void ldmx4(unsigned* r, unsigned addr) {
    asm volatile("ldmatrix.sync.aligned.m8n8.x4.shared.b16 {%0,%1,%2,%3}, [%4];"
        : "=r"(r[0]), "=r"(r[1]), "=r"(r[2]), "=r"(r[3]) : "r"(addr));
}
__device__ __forceinline__ void mma16816(float* c, const unsigned* a, const unsigned* b) {
    asm volatile("mma.sync.aligned.m16n8k16.row.col.f32.bf16.bf16.f32 "
        "{%0,%1,%2,%3}, {%4,%5,%6,%7}, {%8,%9}, {%0,%1,%2,%3};"
        : "+f"(c[0]), "+f"(c[1]), "+f"(c[2]), "+f"(c[3])
        : "r"(a[0]), "r"(a[1]), "r"(a[2]), "r"(a[3]), "r"(b[0]), "r"(b[1]));
}
// branch-free sorted top-4 insert over u32 keys (7-op IMNMX network)
__device__ __forceinline__ void ins4u(unsigned* tt, unsigned kk) {
    unsigned t3 = min(tt[3], kk);
    unsigned a2 = min(tt[2], t3), b3 = max(tt[2], t3);
    unsigned a1 = min(tt[1], a2), b2 = max(tt[1], a2);
    unsigned a0 = min(tt[0], a1), b1 = max(tt[0], a1);
    tt[0] = a0; tt[1] = b1; tt[2] = b2; tt[3] = b3;
}
// quantized int key from scaled distance float (floor = monotone)
__device__ __forceinline__ unsigned mkkey(float kf, int code) {
    int ik;
    asm("cvt.rmi.s32.f32 %0, %1;" : "=r"(ik) : "f"(kf));
    return ((unsigned)(ik + (1 << 21)) << 10) | (unsigned)code;
}

// smem layout for k_pref (bytes). MRG aliases the W tiles (dead after mainloop)
// so total fits 2 CTAs/SM (108544 * 2 = 217088 <= 227KB carveout).
#define RSb 272                       // row stride = 136 halves
#define SM_CN   0
#define SM_XH   4096
#define SM_XL   (4096 + 34816)
#define SM_WH   (4096 + 69632)
#define SM_WL   (4096 + 69632 + 17408)
#define SM_MRG  SM_WH
#define PF_SMEM (SM_WH + 34816)      // 108544

// smem float offsets for k_gcn (4 n-rows per 512-thread block)
#define GA   0
#define GW   640
#define GPN  17536                    // per-n base
#define GPN_STRIDE 9764               // sres 3200 + snsm 3300 + sln 3200 + mu 32 + sd 32
#define GCN_FLOATS (GPN + 4*GPN_STRIDE)   // 56592 floats = 226368 B

// ================================================================ setup
__global__ void k_wconv(const float* __restrict__ emb) {
    int i = blockIdx.x*blockDim.x + threadIdx.x;
    if (i < NQn*NEn*Dn) {
        float x = emb[i];
        __nv_bfloat16 h = __float2bfloat16(x);
        g_wh[i] = h;
        g_wl[i] = __float2bfloat16(__fadd_rn(x, -__bfloat162float(h)));
    }
}
__global__ void k_cnorm(const float* __restrict__ emb) {
    int r = blockIdx.x*(blockDim.x>>5) + (threadIdx.x>>5);
    int lane = threadIdx.x & 31;
    if (r < NQn*NEn) {
        const float* w = emb + (size_t)r*Dn;
        float s = 0.f;
        #pragma unroll
        for (int j = 0; j < 4; j++) { float v = w[lane + 32*j]; s = __fadd_rn(s, __fmul_rn(v, v)); }
        #pragma unroll
        for (int o = 16; o; o >>= 1) s = __fadd_rn(s, __shfl_down_sync(0xffffffffu, s, o));
        if (lane == 0) g_cnorm[r] = s;
    }
}

// ---------------- GCN refine (bit-exact) + fused xnorm; 4 n-rows per block
__global__ __launch_bounds__(512) void k_gcn(const float* __restrict__ A,
        const float* __restrict__ W, const float* __restrict__ bb,
        const float* __restrict__ lns, const float* __restrict__ lnb,
        const float* __restrict__ z, int stage) {
    extern __shared__ float sm[];
    float* sA = sm + GA;
    float* sW = sm + GW;
    int t = threadIdx.x;
    int nn = t >> 7;            // 0..3: which n-row this 128-thread group owns
    int d  = t & 127;
    float* base = sm + GPN + nn*GPN_STRIDE;
    float* sres = base;
    float* snsm = base + 3200;
    float* sln  = base + 6500;
    float* smu  = base + 9700;
    float* ssd  = base + 9732;
    int n = blockIdx.x*4 + nn;
    const float* resg = (stage == 0 ? z : g_res) + (size_t)n*(Vn*Dn);

    for (int i = t; i < Vn*Vn; i += 512) sA[i] = A[i];
    for (int i = t; i < Dn*Dn; i += 512) sW[(i>>7)*132 + (i&127)] = W[i];
    #pragma unroll
    for (int v = 0; v < Vn; v++) sres[v*Dn+d] = resg[v*Dn+d];
    __syncthreads();

    // neigh = A @ res  (k ascending fma chain, SGEMM order)
    {
        float acc[Vn];
        #pragma unroll
        for (int v = 0; v < Vn; v++) acc[v] = 0.f;
        for (int w = 0; w < Vn; w++) {
            float rv = sres[w*Dn+d];
            #pragma unroll
            for (int v = 0; v < Vn; v++) acc[v] = fmaf(sA[v*Vn+w], rv, acc[v]);
        }
        #pragma unroll
        for (int v = 0; v < Vn; v++) snsm[v*132+d] = acc[v];
    }
    __syncthreads();

    // linear (neigh @ W^T) + bias + LeakyReLU ; k ascending fma chain
    {
        float acc[Vn];
        #pragma unroll
        for (int v = 0; v < Vn; v++) acc[v] = 0.f;
        for (int kk = 0; kk < Dn; kk += 4) {
            float4 w4 = *reinterpret_cast<const float4*>(&sW[d*132+kk]);
            #pragma unroll
            for (int v = 0; v < Vn; v++) {
                float4 x4 = *reinterpret_cast<const float4*>(&snsm[v*132+kk]);
                float a = acc[v];
                a = fmaf(x4.x, w4.x, a); a = fmaf(x4.y, w4.y, a);
                a = fmaf(x4.z, w4.z, a); a = fmaf(x4.w, w4.w, a);
                acc[v] = a;
            }
        }
        float bd = bb[d];
        #pragma unroll
        for (int v = 0; v < Vn; v++) {
            float val = __fadd_rn(acc[v], bd);
            val = (val >= 0.f) ? val : __fmul_rn(SLOPEc, val);
            sln[v*Dn+d] = val;
        }
    }
    __syncthreads();

    // LayerNorm stats: warp-per-row within n-group (XLA reduce order)
    {
        int warp = (t >> 5) & 3, lane = t & 31;
        for (int v = warp; v < Vn; v += 4) {
            float s = 0.f;
            #pragma unroll
            for (int j = 0; j < 4; j++) s = __fadd_rn(s, sln[v*Dn + lane + 32*j]);
            #pragma unroll
            for (int o = 16; o; o >>= 1) s = __fadd_rn(s, __shfl_down_sync(0xffffffffu, s, o));
            float mu = __shfl_sync(0xffffffffu, s, 0) * (1.f/Dn);
            float s2 = 0.f;
            #pragma unroll
            for (int j = 0; j < 4; j++) {
                float tt = __fadd_rn(sln[v*Dn + lane + 32*j], -mu);
                s2 = __fadd_rn(s2, __fmul_rn(tt, tt));
            }
            #pragma unroll
            for (int o = 16; o; o >>= 1) s2 = __fadd_rn(s2, __shfl_down_sync(0xffffffffu, s2, o));
            if (lane == 0) { smu[v] = mu; ssd[v] = __fsqrt_rn(__fadd_rn(s2*(1.f/Dn), LNEPSc)); }
        }
    }
    __syncthreads();

    // apply LN + residual add; stash refined^2 into snsm (dead buffer) for xnorm
    {
        float scl = lns[d], bia = lnb[d];
        float* refg = g_ref + (size_t)n*(Vn*Dn);
        #pragma unroll
        for (int v = 0; v < Vn; v++) {
            float a = __fadd_rn(sln[v*Dn+d], -smu[v]);
            float normed = __fadd_rn(__fmul_rn(__fdiv_rn(a, ssd[v]), scl), bia);
            float r = __fadd_rn(sres[v*Dn+d], __fmul_rn(ALPHAc, normed));
            refg[v*Dn+d] = r;
            snsm[v*132+d] = __fmul_rn(r, r);
        }
    }
    __syncthreads();

    // fused xnorm: identical order to standalone (serial j-chain + shfl tree)
    {
        int warp = (t >> 5) & 3, lane = t & 31;
        for (int v = warp; v < Vn; v += 4) {
            float s = 0.f;
            #pragma unroll
            for (int j = 0; j < 4; j++) s = __fadd_rn(s, snsm[v*132 + lane + 32*j]);
            #pragma unroll
            for (int o = 16; o; o >>= 1) s = __fadd_rn(s, __shfl_down_sync(0xffffffffu, s, o));
            if (lane == 0) g_xnorm[n*Vn + v] = s;
        }
    }
}

// ---------------- HMMA prefilter: u32 keys, top-4/lane (IMNMX), uint4 W loads
__global__ __launch_bounds__(256, 2) void k_pref(int stage) {
    extern __shared__ char smc[];
    float* scn = reinterpret_cast<float*>(smc + SM_CN);
    int t = threadIdx.x, wid = t >> 5, lane = t & 31;
    int qbase = blockIdx.x * 128;

    // premultiplied code norms: cn * 2^16 (integer-key domain)
    for (int i = t; i < NEn; i += 256) scn[i] = g_cnorm[stage*NEn + i] * 65536.f;
    // X -> bf16 hi/lo in smem, row stride 136 halves
    for (int i = t; i < 128*Dn; i += 256) {
        int q = i >> 7, k = i & 127;
        float x = g_ref[(size_t)(qbase + q)*Dn + k];
        __nv_bfloat16 h = __float2bfloat16(x);
        __nv_bfloat16 l = __float2bfloat16(__fadd_rn(x, -__bfloat162float(h)));
        *reinterpret_cast<__nv_bfloat16*>(smc + SM_XH + q*RSb + k*2) = h;
        *reinterpret_cast<__nv_bfloat16*>(smc + SM_XL + q*RSb + k*2) = l;
    }

    int q0 = wid * 16;
    unsigned xbh = smem_u32(smc + SM_XH), xbl = smem_u32(smc + SM_XL);
    unsigned wbh = smem_u32(smc + SM_WH), wbl = smem_u32(smc + SM_WL);
    int g = lane >> 3, ri = lane & 7;
    unsigned a_off = (unsigned)((q0 + ri + (g & 1)*8)*RSb + (g >> 1)*16);
    unsigned b_roff = (unsigned)((ri + (g >> 1)*8)*RSb + (g & 1)*16);

    unsigned tlo[4], thi[4];
    #pragma unroll
    for (int j = 0; j < 4; j++) { tlo[j] = 0xFFFFFFFFu; thi[j] = 0xFFFFFFFFu; }

    const unsigned* whp = reinterpret_cast<const unsigned*>(g_wh) + (size_t)stage*65536;
    const unsigned* wlp = reinterpret_cast<const unsigned*>(g_wl) + (size_t)stage*65536;

    for (int chunk = 0; chunk < 16; chunk++) {
        __syncthreads();
        {   // vectorized W tile load: 64 rows x 16 uint4 per array
            const uint4* wh4 = reinterpret_cast<const uint4*>(whp + chunk*4096);
            const uint4* wl4 = reinterpret_cast<const uint4*>(wlp + chunk*4096);
            for (int i = t; i < 64*16; i += 256) {
                int r = i >> 4, c = i & 15;
                *reinterpret_cast<uint4*>(smc + SM_WH + r*RSb + c*16) = wh4[i];
                *reinterpret_cast<uint4*>(smc + SM_WL + r*RSb + c*16) = wl4[i];
            }
        }
        __syncthreads();

        float acc[8][4];
        #pragma unroll
        for (int n = 0; n < 8; n++)
            #pragma unroll
            for (int j = 0; j < 4; j++) acc[n][j] = 0.f;

        #pragma unroll
        for (int kt = 0; kt < 8; kt++) {
            unsigned ah[4], al[4];
            ldmx4(ah, xbh + a_off + kt*32);
            ldmx4(al, xbl + a_off + kt*32);
            #pragma unroll
            for (int np = 0; np < 4; np++) {
                unsigned bh[4], bl[4];
                unsigned bo = (unsigned)(np*16*RSb) + b_roff + kt*32;
                ldmx4(bh, wbh + bo);
                ldmx4(bl, wbl + bo);
                mma16816(acc[np*2],   ah, &bh[0]);
                mma16816(acc[np*2],   ah, &bl[0]);
                mma16816(acc[np*2],   al, &bh[0]);
                mma16816(acc[np*2+1], ah, &bh[2]);
                mma16816(acc[np*2+1], ah, &bl[2]);
                mma16816(acc[np*2+1], al, &bh[2]);
            }
        }
        // epilogue: key = floor(2^16*(cn - 2*acc)) biased, code in low 10 bits
        int cb0 = chunk*64 + (lane & 3)*2;
        #pragma unroll
        for (int nt = 0; nt < 8; nt++) {
            int c0 = cb0 + nt*8;
            float cn0 = scn[c0], cn1 = scn[c0 + 1];
            ins4u(tlo, mkkey(fmaf(-131072.f, acc[nt][0], cn0), c0));
            ins4u(tlo, mkkey(fmaf(-131072.f, acc[nt][1], cn1), c0 + 1));
            ins4u(thi, mkkey(fmaf(-131072.f, acc[nt][2], cn0), c0));
            ins4u(thi, mkkey(fmaf(-131072.f, acc[nt][3], cn1), c0 + 1));
        }
    }

    // merge phase: W tiles are dead; MRG aliases them (barrier orders reuse)
    __syncthreads();
    unsigned* mrg = reinterpret_cast<unsigned*>(smc + SM_MRG);
    {
        int ql = q0 + (lane >> 2), slot = lane & 3;
        #pragma unroll
        for (int j = 0; j < 4; j++) mrg[(ql*4 + slot)*4 + j] = tlo[j];
        int qh = q0 + 8 + (lane >> 2);
        #pragma unroll
        for (int j = 0; j < 4; j++) mrg[(qh*4 + slot)*4 + j] = thi[j];
    }
    __syncthreads();
    if (t < 128) {
        const unsigned* e = &mrg[t*16];
        unsigned best = 0xFFFFFFFFu;
        #pragma unroll
        for (int j = 0; j < 16; j++) best = min(best, e[j]);
        unsigned thr = (best >> 10) + MARGIN_I;
        bool fb = false;
        #pragma unroll
        for (int s = 0; s < 4; s++) if ((e[s*4 + 3] >> 10) <= thr) fb = true;
        int gq = qbase + t, cnt = 0;
        if (fb) {
            g_ccnt[gq] = 255;
        } else {
            #pragma unroll
            for (int j = 0; j < 16; j++) {
                if ((e[j] >> 10) <= thr) {
                    g_cand[(size_t)gq*16 + cnt] = (int)(e[j] & 0x3FFu);
                    cnt++;
                }
            }
            g_ccnt[gq] = cnt;
            if (cnt == 1) g_chosen[gq] = (int)(best & 0x3FFu);
        }
    }
}

// ---------------- exact rescore: thread-per-query fast path; ballot loop for slow
__global__ __launch_bounds__(256) void k_rescore(const float* __restrict__ emb, int stage) {
    int t = threadIdx.x, lane = t & 31;
    int q = blockIdx.x*256 + t;
    int cnt = (q < NVn) ? g_ccnt[q] : 1;
    unsigned slow = __ballot_sync(0xffffffffu, cnt != 1);
    if (!slow) return;
    const float* cb = emb + (size_t)stage*(NEn*Dn);
    const float* cng = g_cnorm + stage*NEn;
    while (slow) {
        int src = __ffs(slow) - 1;
        slow &= slow - 1;
        int sq   = __shfl_sync(0xffffffffu, q, src);
        int scnt = __shfl_sync(0xffffffffu, cnt, src);
        const float* x = g_ref + (size_t)sq*Dn;
        float xn = g_xnorm[sq];
        float bd = 3.4028235e38f; int bi = 0x7fffffff;
        if (scnt <= 16) {
            if (lane < scnt) {
                int c = g_cand[(size_t)sq*16 + lane];
                const float* w = cb + (size_t)c*Dn;
                float acc = 0.f;
                for (int k = 0; k < Dn; k++) acc = fmaf(x[k], w[k], acc);
                bd = __fadd_rn(__fadd_rn(xn, -2.f*acc), cng[c]);
                bi = c;
            }
        } else {
            for (int c = lane; c < NEn; c += 32) {
                const float* w = cb + (size_t)c*Dn;
                float acc = 0.f;
                for (int k = 0; k < Dn; k++) acc = fmaf(x[k], w[k], acc);
                float d = __fadd_rn(__fadd_rn(xn, -2.f*acc), cng[c]);
                if (d < bd) { bd = d; bi = c; }
            }
        }
        #pragma unroll
        for (int o = 16; o; o >>= 1) {
            float od = __shfl_down_sync(0xffffffffu, bd, o);
            int   oi = __shfl_down_sync(0xffffffffu, bi, o);
            if (od < bd || (od == bd && oi < bi)) { bd = od; bi = oi; }
        }
        if (lane == 0) g_chosen[sq] = bi;
    }
}

// ---------------- update (bit-exact): stage0 reads z / writes q; stage3 fused fixup
__global__ __launch_bounds__(256) void k_update(const float* __restrict__ emb, int stage,
        const float* __restrict__ z, float* __restrict__ zq, float* __restrict__ oidx) {
    int t = threadIdx.x;
    int base = blockIdx.x * 64;
    const float* cb = emb + (size_t)stage*(NEn*Dn);
    int v = t >> 2;
    int dseg = t & 3;
    int gvec = base + v;
    int idx = g_chosen[gvec];
    const float* q = cb + (size_t)idx*Dn;
    const float* rsrc = (stage == 0 ? z : g_res) + (size_t)gvec*Dn;
    float* resp = g_res + (size_t)gvec*Dn;
    float* zqp  = zq + (size_t)gvec*Dn;
    const float* zp = z + (size_t)gvec*Dn;
    float ls = 0.f;
    #pragma unroll
    for (int j = 0; j < 8; j++) {
        int dd = dseg*32 + j*4;
        float4 qv = *reinterpret_cast<const float4*>(&q[dd]);
        float4 rv = *reinterpret_cast<const float4*>(&rsrc[dd]);
        float dx = __fadd_rn(qv.x, -rv.x), dy = __fadd_rn(qv.y, -rv.y);
        float dz = __fadd_rn(qv.z, -rv.z), dw = __fadd_rn(qv.w, -rv.w);
        ls = __fadd_rn(ls, __fmul_rn(dx,dx));
        ls = __fadd_rn(ls, __fmul_rn(dy,dy));
        ls = __fadd_rn(ls, __fmul_rn(dz,dz));
        ls = __fadd_rn(ls, __fmul_rn(dw,dw));
        float4 nr = make_float4(__fadd_rn(rv.x,-qv.x), __fadd_rn(rv.y,-qv.y),
                                __fadd_rn(rv.z,-qv.z), __fadd_rn(rv.w,-qv.w));
        *reinterpret_cast<float4*>(&resp[dd]) = nr;
        float4 nz;
        if (stage == 0) {
            nz = qv;                           // 0 + q == q exactly
        } else {
            float4 zv = *reinterpret_cast<const float4*>(&zqp[dd]);
            nz = make_float4(__fadd_rn(zv.x,qv.x), __fadd_rn(zv.y,qv.y),
                             __fadd_rn(zv.z,qv.z), __fadd_rn(zv.w,qv.w));
        }
        if (stage == 3) {                      // straight-through: z + (cum - z)
            float4 zz = *reinterpret_cast<const float4*>(&zp[dd]);
            nz = make_float4(__fadd_rn(zz.x, __fadd_rn(nz.x, -zz.x)),
                             __fadd_rn(zz.y, __fadd_rn(nz.y, -zz.y)),
                             __fadd_rn(zz.z, __fadd_rn(nz.z, -zz.z)),
                             __fadd_rn(zz.w, __fadd_rn(nz.w, -zz.w)));
        }
        *reinterpret_cast<float4*>(&zqp[dd]) = nz;
    }
    #pragma unroll
    for (int o = 2; o; o >>= 1) ls = __fadd_rn(ls, __shfl_down_sync(0xffffffffu, ls, o, 4));
    if (dseg == 0) g_lossv[stage*NVn + gvec] = __fmul_rn(BETA1, ls*(1.f/Dn));
    if (dseg == 1) oidx[(size_t)gvec*NQn + stage] = (float)idx;
}

__global__ void k_loss(float* __restrict__ out) {
    __shared__ float red[1024];
    int t = threadIdx.x;
    float s = 0.f;
    const float4* p = reinterpret_cast<const float4*>(g_lossv);
    for (int i = t; i < (NQn*NVn)/4; i += 1024) {
        float4 v = p[i];
        s = __fadd_rn(s, v.x); s = __fadd_rn(s, v.y);
        s = __fadd_rn(s, v.z); s = __fadd_rn(s, v.w);
    }
    red[t] = s; __syncthreads();
    for (int o = 512; o; o >>= 1) {
        if (t < o) red[t] = __fadd_rn(red[t], red[t+o]);
        __syncthreads();
    }
    if (t == 0) out[0] = red[0] * (1.f/(float)(NQn*NVn));
}

extern "C" void kernel_launch(void* const* d_in, const int* in_sizes, int n_in,
                              void* d_out, int out_size) {
    const float* z   = (const float*)d_in[0];
    const float* emb = (const float*)d_in[1];
    const float* A   = (const float*)d_in[2];
    const float* W   = (const float*)d_in[3];
    const float* b   = (const float*)d_in[4];
    const float* lns = (const float*)d_in[5];
    const float* lnb = (const float*)d_in[6];
    float* out  = (float*)d_out;
    float* zq   = out;
    float* loss = out + (size_t)NVn*Dn;
    float* oidx = loss + 1;

    const int GCN_SMEM = GCN_FLOATS * 4;   // 226368 B
    cudaFuncSetAttribute(k_gcn,  cudaFuncAttributeMaxDynamicSharedMemorySize, GCN_SMEM);
    cudaFuncSetAttribute(k_pref, cudaFuncAttributeMaxDynamicSharedMemorySize, PF_SMEM);

    k_cnorm<<<512, 256>>>(emb);
    k_wconv<<<2048, 256>>>(emb);
    for (int k = 0; k < NQn; k++) {
        k_gcn<<<BTn/4, 512, GCN_SMEM>>>(A, W, b, lns, lnb, z, k);
        k_pref<<<625, 256, PF_SMEM>>>(k);
        k_rescore<<<313, 256>>>(emb, k);
        k_update<<<1250, 256>>>(emb, k, z, zq, oidx);
    }
    k_loss<<<1, 1024>>>(loss);
}

// round 16
// speedup vs baseline: 2.4676x; 1.0473x over previous
#include <cuda_runtime.h>
#include <cuda_bf16.h>

#define BTn 3200
#define Vn 25
#define Dn 128
#define NEn 1024
#define NQn 4
#define NVn (BTn*Vn)          // 80000
#define ALPHAc 0.1f
#define BETA1 1.25f
#define SLOPEc 0.2f
#define LNEPSc 1e-5f
#define MARGIN_I 263          // ceil(4e-3 * 65536): integer-domain margin

// Scratch (allocation-free rule: __device__ globals)
__device__ float g_res[NVn*Dn];
__device__ float g_ref[NVn*Dn];
__device__ float g_xnorm[NVn];
__device__ float g_cnorm[NQn*NEn];
__device__ float g_lossv[NQn*NVn];
__device__ __nv_bfloat16 g_wh[NQn*NEn*Dn];   // codebook hi bf16
__device__ __nv_bfloat16 g_wl[NQn*NEn*Dn];   // codebook lo bf16 (w - hi)
__device__ int g_cand[NVn*16];
__device__ int g_ccnt[NVn];
__device__ int g_chosen[NVn];

__device__ __forceinline__ unsigned smem_u32(const void* p) {
    unsigned a;
    asm("{ .reg .u64 t; cvta.to.shared.u64 t, %1; cvt.u32.u64 %0, t; }"
        : "=r"(a) : "l"(p));
    return a;
}
__device__ __forceinline__ void ldmx4(unsigned* r, unsigned addr) {
    asm volatile("ldmatrix.sync.aligned.m8n8.x4.shared.b16 {%0,%1,%2,%3}, [%4];"
        : "=r"(r[0]), "=r"(r[1]), "=r"(r[2]), "=r"(r[3]) : "r"(addr));
}
__device__ __forceinline__ void mma16816(float* c, const unsigned* a, const unsigned* b) {
    asm volatile("mma.sync.aligned.m16n8k16.row.col.f32.bf16.bf16.f32 "
        "{%0,%1,%2,%3}, {%4,%5,%6,%7}, {%8,%9}, {%0,%1,%2,%3};"
        : "+f"(c[0]), "+f"(c[1]), "+f"(c[2]), "+f"(c[3])
        : "r"(a[0]), "r"(a[1]), "r"(a[2]), "r"(a[3]), "r"(b[0]), "r"(b[1]));
}
// branch-free sorted top-4 insert over u32 keys (7-op IMNMX network)
__device__ __forceinline__ void ins4u(unsigned* tt, unsigned kk) {
    unsigned t3 = min(tt[3], kk);
    unsigned a2 = min(tt[2], t3), b3 = max(tt[2], t3);
    unsigned a1 = min(tt[1], a2), b2 = max(tt[1], a2);
    unsigned a0 = min(tt[0], a1), b1 = max(tt[0], a1);
    tt[0] = a0; tt[1] = b1; tt[2] = b2; tt[3] = b3;
}
// quantized int key from scaled distance float (floor = monotone)
__device__ __forceinline__ unsigned mkkey(float kf, int code) {
    int ik;
    asm("cvt.rmi.s32.f32 %0, %1;" : "=r"(ik) : "f"(kf));
    return ((unsigned)(ik + (1 << 21)) << 10) | (unsigned)code;
}

// smem layout for k_pref (bytes). MRG aliases the W tiles (dead after mainloop)
// so total fits 2 CTAs/SM (108544 * 2 = 217088 <= 227KB carveout).
#define RSb 272                       // row stride = 136 halves
#define SM_CN   0
#define SM_XH   4096
#define SM_XL   (4096 + 34816)
#define SM_WH   (4096 + 69632)
#define SM_WL   (4096 + 69632 + 17408)
#define SM_MRG  SM_WH
#define PF_SMEM (SM_WH + 34816)      // 108544

// smem float offsets for k_gcn (4 n-rows per 512-thread block)
// sWt transposed: [k][d], stride 133 (gcd(133,32)=1 -> conflict-free r/w)
#define GA   0
#define GW   640
#define GPN  (640 + 17024)            // 17664
#define GPN_STRIDE 9764               // sres 3200 + snsm 3300 + sln 3200 + mu 32 + sd 32
#define GCN_FLOATS (GPN + 4*GPN_STRIDE)   // 56720 floats = 226880 B

// ================================================================ setup
__global__ void k_wconv(const float* __restrict__ emb) {
    int i = blockIdx.x*blockDim.x + threadIdx.x;
    if (i < NQn*NEn*Dn) {
        float x = emb[i];
        __nv_bfloat16 h = __float2bfloat16(x);
        g_wh[i] = h;
        g_wl[i] = __float2bfloat16(__fadd_rn(x, -__bfloat162float(h)));
    }
}
__global__ void k_cnorm(const float* __restrict__ emb) {
    int r = blockIdx.x*(blockDim.x>>5) + (threadIdx.x>>5);
    int lane = threadIdx.x & 31;
    if (r < NQn*NEn) {
        const float* w = emb + (size_t)r*Dn;
        float s = 0.f;
        #pragma unroll
        for (int j = 0; j < 4; j++) { float v = w[lane + 32*j]; s = __fadd_rn(s, __fmul_rn(v, v)); }
        #pragma unroll
        for (int o = 16; o; o >>= 1) s = __fadd_rn(s, __shfl_down_sync(0xffffffffu, s, o));
        if (lane == 0) g_cnorm[r] = s;
    }
}

// ---------------- GCN refine (bit-exact) + fused xnorm; 4 n-rows per block
__global__ __launch_bounds__(512) void k_gcn(const float* __restrict__ A,
        const float* __restrict__ W, const float* __restrict__ bb,
        const float* __restrict__ lns, const float* __restrict__ lnb,
        const float* __restrict__ z, int stage) {
    extern __shared__ float sm[];
    float* sA  = sm + GA;
    float* sWt = sm + GW;          // transposed: sWt[k*133 + d]
    int t = threadIdx.x;
    int nn = t >> 7;            // 0..3: which n-row this 128-thread group owns
    int d  = t & 127;
    float* base = sm + GPN + nn*GPN_STRIDE;
    float* sres = base;
    float* snsm = base + 3200;
    float* sln  = base + 6500;
    float* smu  = base + 9700;
    float* ssd  = base + 9732;
    int n = blockIdx.x*4 + nn;
    const float* resg = (stage == 0 ? z : g_res) + (size_t)n*(Vn*Dn);

    for (int i = t; i < Vn*Vn; i += 512) sA[i] = A[i];
    // transposed store: conflict-free (lane addr stride 133)
    for (int i = t; i < Dn*Dn; i += 512) sWt[(i & 127)*133 + (i >> 7)] = W[i];
    #pragma unroll
    for (int v = 0; v < Vn; v++) sres[v*Dn+d] = resg[v*Dn+d];
    __syncthreads();

    // neigh = A @ res  (k ascending fma chain, SGEMM order)
    {
        float acc[Vn];
        #pragma unroll
        for (int v = 0; v < Vn; v++) acc[v] = 0.f;
        for (int w = 0; w < Vn; w++) {
            float rv = sres[w*Dn+d];
            #pragma unroll
            for (int v = 0; v < Vn; v++) acc[v] = fmaf(sA[v*Vn+w], rv, acc[v]);
        }
        #pragma unroll
        for (int v = 0; v < Vn; v++) snsm[v*132+d] = acc[v];
    }
    __syncthreads();

    // linear (neigh @ W^T) + bias + LeakyReLU ; k ascending fma chain
    // W reads now conflict-free scalar LDS (lanes d consecutive)
    {
        float acc[Vn];
        #pragma unroll
        for (int v = 0; v < Vn; v++) acc[v] = 0.f;
        for (int kk = 0; kk < Dn; kk += 4) {
            float w0 = sWt[(kk    )*133 + d];
            float w1 = sWt[(kk + 1)*133 + d];
            float w2 = sWt[(kk + 2)*133 + d];
            float w3 = sWt[(kk + 3)*133 + d];
            #pragma unroll
            for (int v = 0; v < Vn; v++) {
                float4 x4 = *reinterpret_cast<const float4*>(&snsm[v*132+kk]);
                float a = acc[v];
                a = fmaf(x4.x, w0, a); a = fmaf(x4.y, w1, a);
                a = fmaf(x4.z, w2, a); a = fmaf(x4.w, w3, a);
                acc[v] = a;
            }
        }
        float bd = bb[d];
        #pragma unroll
        for (int v = 0; v < Vn; v++) {
            float val = __fadd_rn(acc[v], bd);
            val = (val >= 0.f) ? val : __fmul_rn(SLOPEc, val);
            sln[v*Dn+d] = val;
        }
    }
    __syncthreads();

    // LayerNorm stats: warp-per-row within n-group (XLA reduce order)
    {
        int warp = (t >> 5) & 3, lane = t & 31;
        for (int v = warp; v < Vn; v += 4) {
            float s = 0.f;
            #pragma unroll
            for (int j = 0; j < 4; j++) s = __fadd_rn(s, sln[v*Dn + lane + 32*j]);
            #pragma unroll
            for (int o = 16; o; o >>= 1) s = __fadd_rn(s, __shfl_down_sync(0xffffffffu, s, o));
            float mu = __shfl_sync(0xffffffffu, s, 0) * (1.f/Dn);
            float s2 = 0.f;
            #pragma unroll
            for (int j = 0; j < 4; j++) {
                float tt = __fadd_rn(sln[v*Dn + lane + 32*j], -mu);
                s2 = __fadd_rn(s2, __fmul_rn(tt, tt));
            }
            #pragma unroll
            for (int o = 16; o; o >>= 1) s2 = __fadd_rn(s2, __shfl_down_sync(0xffffffffu, s2, o));
            if (lane == 0) { smu[v] = mu; ssd[v] = __fsqrt_rn(__fadd_rn(s2*(1.f/Dn), LNEPSc)); }
        }
    }
    __syncthreads();

    // apply LN + residual add; stash refined^2 into snsm (dead buffer) for xnorm
    {
        float scl = lns[d], bia = lnb[d];
        float* refg = g_ref + (size_t)n*(Vn*Dn);
        #pragma unroll
        for (int v = 0; v < Vn; v++) {
            float a = __fadd_rn(sln[v*Dn+d], -smu[v]);
            float normed = __fadd_rn(__fmul_rn(__fdiv_rn(a, ssd[v]), scl), bia);
            float r = __fadd_rn(sres[v*Dn+d], __fmul_rn(ALPHAc, normed));
            refg[v*Dn+d] = r;
            snsm[v*132+d] = __fmul_rn(r, r);
        }
    }
    __syncthreads();

    // fused xnorm: identical order to standalone (serial j-chain + shfl tree)
    {
        int warp = (t >> 5) & 3, lane = t & 31;
        for (int v = warp; v < Vn; v += 4) {
            float s = 0.f;
            #pragma unroll
            for (int j = 0; j < 4; j++) s = __fadd_rn(s, snsm[v*132 + lane + 32*j]);
            #pragma unroll
            for (int o = 16; o; o >>= 1) s = __fadd_rn(s, __shfl_down_sync(0xffffffffu, s, o));
            if (lane == 0) g_xnorm[n*Vn + v] = s;
        }
    }
}

// ---------------- HMMA prefilter: u32 keys, top-4/lane (IMNMX), uint4 W loads
__global__ __launch_bounds__(256, 2) void k_pref(int stage) {
    extern __shared__ char smc[];
    float* scn = reinterpret_cast<float*>(smc + SM_CN);
    int t = threadIdx.x, wid = t >> 5, lane = t & 31;
    int qbase = blockIdx.x * 128;

    // premultiplied code norms: cn * 2^16 (integer-key domain)
    for (int i = t; i < NEn; i += 256) scn[i] = g_cnorm[stage*NEn + i] * 65536.f;
    // X -> bf16 hi/lo in smem, row stride 136 halves
    for (int i = t; i < 128*Dn; i += 256) {
        int q = i >> 7, k = i & 127;
        float x = g_ref[(size_t)(qbase + q)*Dn + k];
        __nv_bfloat16 h = __float2bfloat16(x);
        __nv_bfloat16 l = __float2bfloat16(__fadd_rn(x, -__bfloat162float(h)));
        *reinterpret_cast<__nv_bfloat16*>(smc + SM_XH + q*RSb + k*2) = h;
        *reinterpret_cast<__nv_bfloat16*>(smc + SM_XL + q*RSb + k*2) = l;
    }

    int q0 = wid * 16;
    unsigned xbh = smem_u32(smc + SM_XH), xbl = smem_u32(smc + SM_XL);
    unsigned wbh = smem_u32(smc + SM_WH), wbl = smem_u32(smc + SM_WL);
    int g = lane >> 3, ri = lane & 7;
    unsigned a_off = (unsigned)((q0 + ri + (g & 1)*8)*RSb + (g >> 1)*16);
    unsigned b_roff = (unsigned)((ri + (g >> 1)*8)*RSb + (g & 1)*16);

    unsigned tlo[4], thi[4];
    #pragma unroll
    for (int j = 0; j < 4; j++) { tlo[j] = 0xFFFFFFFFu; thi[j] = 0xFFFFFFFFu; }

    const unsigned* whp = reinterpret_cast<const unsigned*>(g_wh) + (size_t)stage*65536;
    const unsigned* wlp = reinterpret_cast<const unsigned*>(g_wl) + (size_t)stage*65536;

    for (int chunk = 0; chunk < 16; chunk++) {
        __syncthreads();
        {   // vectorized W tile load: 64 rows x 16 uint4 per array
            const uint4* wh4 = reinterpret_cast<const uint4*>(whp + chunk*4096);
            const uint4* wl4 = reinterpret_cast<const uint4*>(wlp + chunk*4096);
            for (int i = t; i < 64*16; i += 256) {
                int r = i >> 4, c = i & 15;
                *reinterpret_cast<uint4*>(smc + SM_WH + r*RSb + c*16) = wh4[i];
                *reinterpret_cast<uint4*>(smc + SM_WL + r*RSb + c*16) = wl4[i];
            }
        }
        __syncthreads();

        float acc[8][4];
        #pragma unroll
        for (int n = 0; n < 8; n++)
            #pragma unroll
            for (int j = 0; j < 4; j++) acc[n][j] = 0.f;

        #pragma unroll
        for (int kt = 0; kt < 8; kt++) {
            unsigned ah[4], al[4];
            ldmx4(ah, xbh + a_off + kt*32);
            ldmx4(al, xbl + a_off + kt*32);
            #pragma unroll
            for (int np = 0; np < 4; np++) {
                unsigned bh[4], bl[4];
                unsigned bo = (unsigned)(np*16*RSb) + b_roff + kt*32;
                ldmx4(bh, wbh + bo);
                ldmx4(bl, wbl + bo);
                mma16816(acc[np*2],   ah, &bh[0]);
                mma16816(acc[np*2],   ah, &bl[0]);
                mma16816(acc[np*2],   al, &bh[0]);
                mma16816(acc[np*2+1], ah, &bh[2]);
                mma16816(acc[np*2+1], ah, &bl[2]);
                mma16816(acc[np*2+1], al, &bh[2]);
            }
        }
        // epilogue: key = floor(2^16*(cn - 2*acc)) biased, code in low 10 bits
        int cb0 = chunk*64 + (lane & 3)*2;
        #pragma unroll
        for (int nt = 0; nt < 8; nt++) {
            int c0 = cb0 + nt*8;
            float cn0 = scn[c0], cn1 = scn[c0 + 1];
            ins4u(tlo, mkkey(fmaf(-131072.f, acc[nt][0], cn0), c0));
            ins4u(tlo, mkkey(fmaf(-131072.f, acc[nt][1], cn1), c0 + 1));
            ins4u(thi, mkkey(fmaf(-131072.f, acc[nt][2], cn0), c0));
            ins4u(thi, mkkey(fmaf(-131072.f, acc[nt][3], cn1), c0 + 1));
        }
    }

    // merge phase: W tiles are dead; MRG aliases them (barrier orders reuse)
    __syncthreads();
    unsigned* mrg = reinterpret_cast<unsigned*>(smc + SM_MRG);
    {
        int ql = q0 + (lane >> 2), slot = lane & 3;
        #pragma unroll
        for (int j = 0; j < 4; j++) mrg[(ql*4 + slot)*4 + j] = tlo[j];
        int qh = q0 + 8 + (lane >> 2);
        #pragma unroll
        for (int j = 0; j < 4; j++) mrg[(qh*4 + slot)*4 + j] = thi[j];
    }
    __syncthreads();
    if (t < 128) {
        const unsigned* e = &mrg[t*16];
        unsigned best = 0xFFFFFFFFu;
        #pragma unroll
        for (int j = 0; j < 16; j++) best = min(best, e[j]);
        unsigned thr = (best >> 10) + MARGIN_I;
        bool fb = false;
        #pragma unroll
        for (int s = 0; s < 4; s++) if ((e[s*4 + 3] >> 10) <= thr) fb = true;
        int gq = qbase + t, cnt = 0;
        if (fb) {
            g_ccnt[gq] = 255;
        } else {
            #pragma unroll
            for (int j = 0; j < 16; j++) {
                if ((e[j] >> 10) <= thr) {
                    g_cand[(size_t)gq*16 + cnt] = (int)(e[j] & 0x3FFu);
                    cnt++;
                }
            }
            g_ccnt[gq] = cnt;
            if (cnt == 1) g_chosen[gq] = (int)(best & 0x3FFu);
        }
    }
}

// ---------------- update (bit-exact) with fused exact rescore (warps 0-1)
__global__ __launch_bounds__(256) void k_update(const float* __restrict__ emb, int stage,
        const float* __restrict__ z, float* __restrict__ zq, float* __restrict__ oidx) {
    int t = threadIdx.x;
    int base = blockIdx.x * 64;
    const float* cb = emb + (size_t)stage*(NEn*Dn);

    // fused rescore: resolve this block's 64 queries (most already chosen)
    if (t < 64) {
        int lane = t & 31;
        int q = base + t;
        int cnt = g_ccnt[q];
        const float* cng = g_cnorm + stage*NEn;
        unsigned slow = __ballot_sync(0xffffffffu, cnt != 1);
        while (slow) {
            int src = __ffs(slow) - 1;
            slow &= slow - 1;
            int sq   = __shfl_sync(0xffffffffu, q, src);
            int scnt = __shfl_sync(0xffffffffu, cnt, src);
            const float* x = g_ref + (size_t)sq*Dn;
            float xn = g_xnorm[sq];
            float bd = 3.4028235e38f; int bi = 0x7fffffff;
            if (scnt <= 16) {
                if (lane < scnt) {
                    int c = g_cand[(size_t)sq*16 + lane];
                    const float* w = cb + (size_t)c*Dn;
                    float acc = 0.f;
                    for (int k = 0; k < Dn; k++) acc = fmaf(x[k], w[k], acc);
                    bd = __fadd_rn(__fadd_rn(xn, -2.f*acc), cng[c]);
                    bi = c;
                }
            } else {
                for (int c = lane; c < NEn; c += 32) {
                    const float* w = cb + (size_t)c*Dn;
                    float acc = 0.f;
                    for (int k = 0; k < Dn; k++) acc = fmaf(x[k], w[k], acc);
                    float d = __fadd_rn(__fadd_rn(xn, -2.f*acc), cng[c]);
                    if (d < bd) { bd = d; bi = c; }
                }
            }
            #pragma unroll
            for (int o = 16; o; o >>= 1) {
                float od = __shfl_down_sync(0xffffffffu, bd, o);
                int   oi = __shfl_down_sync(0xffffffffu, bi, o);
                if (od < bd || (od == bd && oi < bi)) { bd = od; bi = oi; }
            }
            if (lane == 0) g_chosen[sq] = bi;
        }
    }
    __syncthreads();

    int v = t >> 2;
    int dseg = t & 3;
    int gvec = base + v;
    int idx = g_chosen[gvec];
    const float* q = cb + (size_t)idx*Dn;
    const float* rsrc = (stage == 0 ? z : g_res) + (size_t)gvec*Dn;
    float* resp = g_res + (size_t)gvec*Dn;
    float* zqp  = zq + (size_t)gvec*Dn;
    const float* zp = z + (size_t)gvec*Dn;
    float ls = 0.f;
    #pragma unroll
    for (int j = 0; j < 8; j++) {
        int dd = dseg*32 + j*4;
        float4 qv = *reinterpret_cast<const float4*>(&q[dd]);
        float4 rv = *reinterpret_cast<const float4*>(&rsrc[dd]);
        float dx = __fadd_rn(qv.x, -rv.x), dy = __fadd_rn(qv.y, -rv.y);
        float dz = __fadd_rn(qv.z, -rv.z), dw = __fadd_rn(qv.w, -rv.w);
        ls = __fadd_rn(ls, __fmul_rn(dx,dx));
        ls = __fadd_rn(ls, __fmul_rn(dy,dy));
        ls = __fadd_rn(ls, __fmul_rn(dz,dz));
        ls = __fadd_rn(ls, __fmul_rn(dw,dw));
        float4 nr = make_float4(__fadd_rn(rv.x,-qv.x), __fadd_rn(rv.y,-qv.y),
                                __fadd_rn(rv.z,-qv.z), __fadd_rn(rv.w,-qv.w));
        *reinterpret_cast<float4*>(&resp[dd]) = nr;
        float4 nz;
        if (stage == 0) {
            nz = qv;                           // 0 + q == q exactly
        } else {
            float4 zv = *reinterpret_cast<const float4*>(&zqp[dd]);
            nz = make_float4(__fadd_rn(zv.x,qv.x), __fadd_rn(zv.y,qv.y),
                             __fadd_rn(zv.z,qv.z), __fadd_rn(zv.w,qv.w));
        }
        if (stage == 3) {                      // straight-through: z + (cum - z)
            float4 zz = *reinterpret_cast<const float4*>(&zp[dd]);
            nz = make_float4(__fadd_rn(zz.x, __fadd_rn(nz.x, -zz.x)),
                             __fadd_rn(zz.y, __fadd_rn(nz.y, -zz.y)),
                             __fadd_rn(zz.z, __fadd_rn(nz.z, -zz.z)),
                             __fadd_rn(zz.w, __fadd_rn(nz.w, -zz.w)));
        }
        *reinterpret_cast<float4*>(&zqp[dd]) = nz;
    }
    #pragma unroll
    for (int o = 2; o; o >>= 1) ls = __fadd_rn(ls, __shfl_down_sync(0xffffffffu, ls, o, 4));
    if (dseg == 0) g_lossv[stage*NVn + gvec] = __fmul_rn(BETA1, ls*(1.f/Dn));
    if (dseg == 1) oidx[(size_t)gvec*NQn + stage] = (float)idx;
}

__global__ void k_loss(float* __restrict__ out) {
    __shared__ float red[1024];
    int t = threadIdx.x;
    float s = 0.f;
    const float4* p = reinterpret_cast<const float4*>(g_lossv);
    for (int i = t; i < (NQn*NVn)/4; i += 1024) {
        float4 v = p[i];
        s = __fadd_rn(s, v.x); s = __fadd_rn(s, v.y);
        s = __fadd_rn(s, v.z); s = __fadd_rn(s, v.w);
    }
    red[t] = s; __syncthreads();
    for (int o = 512; o; o >>= 1) {
        if (t < o) red[t] = __fadd_rn(red[t], red[t+o]);
        __syncthreads();
    }
    if (t == 0) out[0] = red[0] * (1.f/(float)(NQn*NVn));
}

extern "C" void kernel_launch(void* const* d_in, const int* in_sizes, int n_in,
                              void* d_out, int out_size) {
    const float* z   = (const float*)d_in[0];
    const float* emb = (const float*)d_in[1];
    const float* A   = (const float*)d_in[2];
    const float* W   = (const float*)d_in[3];
    const float* b   = (const float*)d_in[4];
    const float* lns = (const float*)d_in[5];
    const float* lnb = (const float*)d_in[6];
    float* out  = (float*)d_out;
    float* zq   = out;
    float* loss = out + (size_t)NVn*Dn;
    float* oidx = loss + 1;

    const int GCN_SMEM = GCN_FLOATS * 4;   // 226880 B
    cudaFuncSetAttribute(k_gcn,  cudaFuncAttributeMaxDynamicSharedMemorySize, GCN_SMEM);
    cudaFuncSetAttribute(k_pref, cudaFuncAttributeMaxDynamicSharedMemorySize, PF_SMEM);

    k_cnorm<<<512, 256>>>(emb);
    k_wconv<<<2048, 256>>>(emb);
    for (int k = 0; k < NQn; k++) {
        k_gcn<<<BTn/4, 512, GCN_SMEM>>>(A, W, b, lns, lnb, z, k);
        k_pref<<<625, 256, PF_SMEM>>>(k);
        k_update<<<1250, 256>>>(emb, k, z, zq, oidx);
    }
    k_loss<<<1, 1024>>>(loss);
}

// round 17
// speedup vs baseline: 2.5097x; 1.0171x over previous
#include <cuda_runtime.h>
#include <cuda_bf16.h>

#define BTn 3200
#define Vn 25
#define Dn 128
#define NEn 1024
#define NQn 4
#define NVn (BTn*Vn)          // 80000
#define ALPHAc 0.1f
#define BETA1 1.25f
#define SLOPEc 0.2f
#define LNEPSc 1e-5f
#define MARGIN_I 263          // ceil(4e-3 * 65536): integer-domain margin

// Scratch (allocation-free rule: __device__ globals)
__device__ float g_res[NVn*Dn];
__device__ float g_ref[NVn*Dn];
__device__ __nv_bfloat16 g_refh[NVn*Dn];     // bf16 hi of refined (fused in k_gcn)
__device__ __nv_bfloat16 g_refl[NVn*Dn];     // bf16 lo of refined
__device__ float g_xnorm[NVn];
__device__ float g_cnorm[NQn*NEn];
__device__ float g_lossv[NQn*NVn];
__device__ float g_lpart[80];
__device__ __nv_bfloat16 g_wh[NQn*NEn*Dn];   // codebook hi bf16
__device__ __nv_bfloat16 g_wl[NQn*NEn*Dn];   // codebook lo bf16 (w - hi)
__device__ int g_cand[NVn*16];
__device__ int g_ccnt[NVn];
__device__ int g_chosen[NVn];

__device__ __forceinline__ unsigned smem_u32(const void* p) {
    unsigned a;
    asm("{ .reg .u64 t; cvta.to.shared.u64 t, %1; cvt.u32.u64 %0, t; }"
        : "=r"(a) : "l"(p));
    return a;
}
__device__ __forceinline__ void ldmx4(unsigned* r, unsigned addr) {
    asm volatile("ldmatrix.sync.aligned.m8n8.x4.shared.b16 {%0,%1,%2,%3}, [%4];"
        : "=r"(r[0]), "=r"(r[1]), "=r"(r[2]), "=r"(r[3]) : "r"(addr));
}
__device__ __forceinline__ void mma16816(float* c, const unsigned* a, const unsigned* b) {
    asm volatile("mma.sync.aligned.m16n8k16.row.col.f32.bf16.bf16.f32 "
        "{%0,%1,%2,%3}, {%4,%5,%6,%7}, {%8,%9}, {%0,%1,%2,%3};"
        : "+f"(c[0]), "+f"(c[1]), "+f"(c[2]), "+f"(c[3])
        : "r"(a[0]), "r"(a[1]), "r"(a[2]), "r"(a[3]), "r"(b[0]), "r"(b[1]));
}
// branch-free sorted top-4 insert over u32 keys (7-op IMNMX network)
__device__ __forceinline__ void ins4u(unsigned* tt, unsigned kk) {
    unsigned t3 = min(tt[3], kk);
    unsigned a2 = min(tt[2], t3), b3 = max(tt[2], t3);
    unsigned a1 = min(tt[1], a2), b2 = max(tt[1], a2);
    unsigned a0 = min(tt[0], a1), b1 = max(tt[0], a1);
    tt[0] = a0; tt[1] = b1; tt[2] = b2; tt[3] = b3;
}
// quantized int key from scaled distance float (floor = monotone)
__device__ __forceinline__ unsigned mkkey(float kf, int code) {
    int ik;
    asm("cvt.rmi.s32.f32 %0, %1;" : "=r"(ik) : "f"(kf));
    return ((unsigned)(ik + (1 << 21)) << 10) | (unsigned)code;
}

// smem layout for k_pref (bytes). MRG aliases the W tiles (dead after mainloop)
// so total fits 2 CTAs/SM (108544 * 2 = 217088 <= 227KB carveout).
#define RSb 272                       // row stride = 136 halves
#define SM_CN   0
#define SM_XH   4096
#define SM_XL   (4096 + 34816)
#define SM_WH   (4096 + 69632)
#define SM_WL   (4096 + 69632 + 17408)
#define SM_MRG  SM_WH
#define PF_SMEM (SM_WH + 34816)      // 108544

// smem float offsets for k_gcn (4 n-rows per 512-thread block)
// sWt transposed: [k][d], stride 133 (gcd(133,32)=1 -> conflict-free r/w)
#define GA   0
#define GW   640
#define GPN  (640 + 17024)            // 17664
#define GPN_STRIDE 9764               // sres 3200 + snsm 3300 + sln 3200 + mu 32 + sd 32
#define GCN_FLOATS (GPN + 4*GPN_STRIDE)   // 56720 floats = 226880 B

// ================================================================ setup
__global__ void k_wconv(const float* __restrict__ emb) {
    int i = blockIdx.x*blockDim.x + threadIdx.x;
    if (i < NQn*NEn*Dn) {
        float x = emb[i];
        __nv_bfloat16 h = __float2bfloat16(x);
        g_wh[i] = h;
        g_wl[i] = __float2bfloat16(__fadd_rn(x, -__bfloat162float(h)));
    }
}
__global__ void k_cnorm(const float* __restrict__ emb) {
    int r = blockIdx.x*(blockDim.x>>5) + (threadIdx.x>>5);
    int lane = threadIdx.x & 31;
    if (r < NQn*NEn) {
        const float* w = emb + (size_t)r*Dn;
        float s = 0.f;
        #pragma unroll
        for (int j = 0; j < 4; j++) { float v = w[lane + 32*j]; s = __fadd_rn(s, __fmul_rn(v, v)); }
        #pragma unroll
        for (int o = 16; o; o >>= 1) s = __fadd_rn(s, __shfl_down_sync(0xffffffffu, s, o));
        if (lane == 0) g_cnorm[r] = s;
    }
}

// ---------------- GCN refine (bit-exact) + fused xnorm + fused bf16 split
__global__ __launch_bounds__(512) void k_gcn(const float* __restrict__ A,
        const float* __restrict__ W, const float* __restrict__ bb,
        const float* __restrict__ lns, const float* __restrict__ lnb,
        const float* __restrict__ z, int stage) {
    extern __shared__ float sm[];
    float* sA  = sm + GA;
    float* sWt = sm + GW;          // transposed: sWt[k*133 + d]
    int t = threadIdx.x;
    int nn = t >> 7;            // 0..3: which n-row this 128-thread group owns
    int d  = t & 127;
    float* base = sm + GPN + nn*GPN_STRIDE;
    float* sres = base;
    float* snsm = base + 3200;
    float* sln  = base + 6500;
    float* smu  = base + 9700;
    float* ssd  = base + 9732;
    int n = blockIdx.x*4 + nn;
    const float* resg = (stage == 0 ? z : g_res) + (size_t)n*(Vn*Dn);

    for (int i = t; i < Vn*Vn; i += 512) sA[i] = A[i];
    // transposed store: conflict-free (lane addr stride 133)
    for (int i = t; i < Dn*Dn; i += 512) sWt[(i & 127)*133 + (i >> 7)] = W[i];
    #pragma unroll
    for (int v = 0; v < Vn; v++) sres[v*Dn+d] = resg[v*Dn+d];
    __syncthreads();

    // neigh = A @ res  (k ascending fma chain, SGEMM order)
    {
        float acc[Vn];
        #pragma unroll
        for (int v = 0; v < Vn; v++) acc[v] = 0.f;
        for (int w = 0; w < Vn; w++) {
            float rv = sres[w*Dn+d];
            #pragma unroll
            for (int v = 0; v < Vn; v++) acc[v] = fmaf(sA[v*Vn+w], rv, acc[v]);
        }
        #pragma unroll
        for (int v = 0; v < Vn; v++) snsm[v*132+d] = acc[v];
    }
    __syncthreads();

    // linear (neigh @ W^T) + bias + LeakyReLU ; k ascending fma chain
    {
        float acc[Vn];
        #pragma unroll
        for (int v = 0; v < Vn; v++) acc[v] = 0.f;
        for (int kk = 0; kk < Dn; kk += 4) {
            float w0 = sWt[(kk    )*133 + d];
            float w1 = sWt[(kk + 1)*133 + d];
            float w2 = sWt[(kk + 2)*133 + d];
            float w3 = sWt[(kk + 3)*133 + d];
            #pragma unroll
            for (int v = 0; v < Vn; v++) {
                float4 x4 = *reinterpret_cast<const float4*>(&snsm[v*132+kk]);
                float a = acc[v];
                a = fmaf(x4.x, w0, a); a = fmaf(x4.y, w1, a);
                a = fmaf(x4.z, w2, a); a = fmaf(x4.w, w3, a);
                acc[v] = a;
            }
        }
        float bd = bb[d];
        #pragma unroll
        for (int v = 0; v < Vn; v++) {
            float val = __fadd_rn(acc[v], bd);
            val = (val >= 0.f) ? val : __fmul_rn(SLOPEc, val);
            sln[v*Dn+d] = val;
        }
    }
    __syncthreads();

    // LayerNorm stats: warp-per-row within n-group (XLA reduce order)
    {
        int warp = (t >> 5) & 3, lane = t & 31;
        for (int v = warp; v < Vn; v += 4) {
            float s = 0.f;
            #pragma unroll
            for (int j = 0; j < 4; j++) s = __fadd_rn(s, sln[v*Dn + lane + 32*j]);
            #pragma unroll
            for (int o = 16; o; o >>= 1) s = __fadd_rn(s, __shfl_down_sync(0xffffffffu, s, o));
            float mu = __shfl_sync(0xffffffffu, s, 0) * (1.f/Dn);
            float s2 = 0.f;
            #pragma unroll
            for (int j = 0; j < 4; j++) {
                float tt = __fadd_rn(sln[v*Dn + lane + 32*j], -mu);
                s2 = __fadd_rn(s2, __fmul_rn(tt, tt));
            }
            #pragma unroll
            for (int o = 16; o; o >>= 1) s2 = __fadd_rn(s2, __shfl_down_sync(0xffffffffu, s2, o));
            if (lane == 0) { smu[v] = mu; ssd[v] = __fsqrt_rn(__fadd_rn(s2*(1.f/Dn), LNEPSc)); }
        }
    }
    __syncthreads();

    // apply LN + residual add; write ref (fp32) + bf16 hi/lo; stash r^2 for xnorm
    {
        float scl = lns[d], bia = lnb[d];
        size_t rb = (size_t)n*(Vn*Dn);
        float* refg = g_ref + rb;
        __nv_bfloat16* rhg = g_refh + rb;
        __nv_bfloat16* rlg = g_refl + rb;
        #pragma unroll
        for (int v = 0; v < Vn; v++) {
            float a = __fadd_rn(sln[v*Dn+d], -smu[v]);
            float normed = __fadd_rn(__fmul_rn(__fdiv_rn(a, ssd[v]), scl), bia);
            float r = __fadd_rn(sres[v*Dn+d], __fmul_rn(ALPHAc, normed));
            refg[v*Dn+d] = r;
            __nv_bfloat16 h = __float2bfloat16(r);
            rhg[v*Dn+d] = h;
            rlg[v*Dn+d] = __float2bfloat16(__fadd_rn(r, -__bfloat162float(h)));
            snsm[v*132+d] = __fmul_rn(r, r);
        }
    }
    __syncthreads();

    // fused xnorm: identical order to standalone (serial j-chain + shfl tree)
    {
        int warp = (t >> 5) & 3, lane = t & 31;
        for (int v = warp; v < Vn; v += 4) {
            float s = 0.f;
            #pragma unroll
            for (int j = 0; j < 4; j++) s = __fadd_rn(s, snsm[v*132 + lane + 32*j]);
            #pragma unroll
            for (int o = 16; o; o >>= 1) s = __fadd_rn(s, __shfl_down_sync(0xffffffffu, s, o));
            if (lane == 0) g_xnorm[n*Vn + v] = s;
        }
    }
}

// ---------------- HMMA prefilter: u32 keys, top-4/lane (IMNMX), uint4 loads
__global__ __launch_bounds__(256, 2) void k_pref(int stage) {
    extern __shared__ char smc[];
    float* scn = reinterpret_cast<float*>(smc + SM_CN);
    int t = threadIdx.x, wid = t >> 5, lane = t & 31;
    int qbase = blockIdx.x * 128;

    // premultiplied code norms: cn * 2^16 (integer-key domain)
    for (int i = t; i < NEn; i += 256) scn[i] = g_cnorm[stage*NEn + i] * 65536.f;
    // X tiles: direct bf16 hi/lo from k_gcn, uint4 vectorized (16 rows x 16 u4)
    {
        const uint4* xh4 = reinterpret_cast<const uint4*>(g_refh + (size_t)qbase*Dn);
        const uint4* xl4 = reinterpret_cast<const uint4*>(g_refl + (size_t)qbase*Dn);
        for (int i = t; i < 128*16; i += 256) {
            int q = i >> 4, c = i & 15;
            *reinterpret_cast<uint4*>(smc + SM_XH + q*RSb + c*16) = xh4[i];
            *reinterpret_cast<uint4*>(smc + SM_XL + q*RSb + c*16) = xl4[i];
        }
    }

    int q0 = wid * 16;
    unsigned xbh = smem_u32(smc + SM_XH), xbl = smem_u32(smc + SM_XL);
    unsigned wbh = smem_u32(smc + SM_WH), wbl = smem_u32(smc + SM_WL);
    int g = lane >> 3, ri = lane & 7;
    unsigned a_off = (unsigned)((q0 + ri + (g & 1)*8)*RSb + (g >> 1)*16);
    unsigned b_roff = (unsigned)((ri + (g >> 1)*8)*RSb + (g & 1)*16);

    unsigned tlo[4], thi[4];
    #pragma unroll
    for (int j = 0; j < 4; j++) { tlo[j] = 0xFFFFFFFFu; thi[j] = 0xFFFFFFFFu; }

    const unsigned* whp = reinterpret_cast<const unsigned*>(g_wh) + (size_t)stage*65536;
    const unsigned* wlp = reinterpret_cast<const unsigned*>(g_wl) + (size_t)stage*65536;

    for (int chunk = 0; chunk < 16; chunk++) {
        __syncthreads();
        {   // vectorized W tile load: 64 rows x 16 uint4 per array
            const uint4* wh4 = reinterpret_cast<const uint4*>(whp + chunk*4096);
            const uint4* wl4 = reinterpret_cast<const uint4*>(wlp + chunk*4096);
            for (int i = t; i < 64*16; i += 256) {
                int r = i >> 4, c = i & 15;
                *reinterpret_cast<uint4*>(smc + SM_WH + r*RSb + c*16) = wh4[i];
                *reinterpret_cast<uint4*>(smc + SM_WL + r*RSb + c*16) = wl4[i];
            }
        }
        __syncthreads();

        float acc[8][4];
        #pragma unroll
        for (int n = 0; n < 8; n++)
            #pragma unroll
            for (int j = 0; j < 4; j++) acc[n][j] = 0.f;

        #pragma unroll
        for (int kt = 0; kt < 8; kt++) {
            unsigned ah[4], al[4];
            ldmx4(ah, xbh + a_off + kt*32);
            ldmx4(al, xbl + a_off + kt*32);
            #pragma unroll
            for (int np = 0; np < 4; np++) {
                unsigned bh[4], bl[4];
                unsigned bo = (unsigned)(np*16*RSb) + b_roff + kt*32;
                ldmx4(bh, wbh + bo);
                ldmx4(bl, wbl + bo);
                mma16816(acc[np*2],   ah, &bh[0]);
                mma16816(acc[np*2],   ah, &bl[0]);
                mma16816(acc[np*2],   al, &bh[0]);
                mma16816(acc[np*2+1], ah, &bh[2]);
                mma16816(acc[np*2+1], ah, &bl[2]);
                mma16816(acc[np*2+1], al, &bh[2]);
            }
        }
        // epilogue: key = floor(2^16*(cn - 2*acc)) biased, code in low 10 bits
        int cb0 = chunk*64 + (lane & 3)*2;
        #pragma unroll
        for (int nt = 0; nt < 8; nt++) {
            int c0 = cb0 + nt*8;
            float cn0 = scn[c0], cn1 = scn[c0 + 1];
            ins4u(tlo, mkkey(fmaf(-131072.f, acc[nt][0], cn0), c0));
            ins4u(tlo, mkkey(fmaf(-131072.f, acc[nt][1], cn1), c0 + 1));
            ins4u(thi, mkkey(fmaf(-131072.f, acc[nt][2], cn0), c0));
            ins4u(thi, mkkey(fmaf(-131072.f, acc[nt][3], cn1), c0 + 1));
        }
    }

    // merge phase: W tiles are dead; MRG aliases them (barrier orders reuse)
    __syncthreads();
    unsigned* mrg = reinterpret_cast<unsigned*>(smc + SM_MRG);
    {
        int ql = q0 + (lane >> 2), slot = lane & 3;
        #pragma unroll
        for (int j = 0; j < 4; j++) mrg[(ql*4 + slot)*4 + j] = tlo[j];
        int qh = q0 + 8 + (lane >> 2);
        #pragma unroll
        for (int j = 0; j < 4; j++) mrg[(qh*4 + slot)*4 + j] = thi[j];
    }
    __syncthreads();
    if (t < 128) {
        const unsigned* e = &mrg[t*16];
        unsigned best = 0xFFFFFFFFu;
        #pragma unroll
        for (int j = 0; j < 16; j++) best = min(best, e[j]);
        unsigned thr = (best >> 10) + MARGIN_I;
        bool fb = false;
        #pragma unroll
        for (int s = 0; s < 4; s++) if ((e[s*4 + 3] >> 10) <= thr) fb = true;
        int gq = qbase + t, cnt = 0;
        if (fb) {
            g_ccnt[gq] = 255;
        } else {
            #pragma unroll
            for (int j = 0; j < 16; j++) {
                if ((e[j] >> 10) <= thr) {
                    g_cand[(size_t)gq*16 + cnt] = (int)(e[j] & 0x3FFu);
                    cnt++;
                }
            }
            g_ccnt[gq] = cnt;
            if (cnt == 1) g_chosen[gq] = (int)(best & 0x3FFu);
        }
    }
}

// ---------------- update (bit-exact) with fused exact rescore (warps 0-1)
__global__ __launch_bounds__(256) void k_update(const float* __restrict__ emb, int stage,
        const float* __restrict__ z, float* __restrict__ zq, float* __restrict__ oidx) {
    int t = threadIdx.x;
    int base = blockIdx.x * 64;
    const float* cb = emb + (size_t)stage*(NEn*Dn);

    // fused rescore: resolve this block's 64 queries (most already chosen)
    if (t < 64) {
        int lane = t & 31;
        int q = base + t;
        int cnt = g_ccnt[q];
        const float* cng = g_cnorm + stage*NEn;
        unsigned slow = __ballot_sync(0xffffffffu, cnt != 1);
        while (slow) {
            int src = __ffs(slow) - 1;
            slow &= slow - 1;
            int sq   = __shfl_sync(0xffffffffu, q, src);
            int scnt = __shfl_sync(0xffffffffu, cnt, src);
            const float* x = g_ref + (size_t)sq*Dn;
            float xn = g_xnorm[sq];
            float bd = 3.4028235e38f; int bi = 0x7fffffff;
            if (scnt <= 16) {
                if (lane < scnt) {
                    int c = g_cand[(size_t)sq*16 + lane];
                    const float* w = cb + (size_t)c*Dn;
                    float acc = 0.f;
                    for (int k = 0; k < Dn; k++) acc = fmaf(x[k], w[k], acc);
                    bd = __fadd_rn(__fadd_rn(xn, -2.f*acc), cng[c]);
                    bi = c;
                }
            } else {
                for (int c = lane; c < NEn; c += 32) {
                    const float* w = cb + (size_t)c*Dn;
                    float acc = 0.f;
                    for (int k = 0; k < Dn; k++) acc = fmaf(x[k], w[k], acc);
                    float d = __fadd_rn(__fadd_rn(xn, -2.f*acc), cng[c]);
                    if (d < bd) { bd = d; bi = c; }
                }
            }
            #pragma unroll
            for (int o = 16; o; o >>= 1) {
                float od = __shfl_down_sync(0xffffffffu, bd, o);
                int   oi = __shfl_down_sync(0xffffffffu, bi, o);
                if (od < bd || (od == bd && oi < bi)) { bd = od; bi = oi; }
            }
            if (lane == 0) g_chosen[sq] = bi;
        }
    }
    __syncthreads();

    int v = t >> 2;
    int dseg = t & 3;
    int gvec = base + v;
    int idx = g_chosen[gvec];
    const float* q = cb + (size_t)idx*Dn;
    const float* rsrc = (stage == 0 ? z : g_res) + (size_t)gvec*Dn;
    float* resp = g_res + (size_t)gvec*Dn;
    float* zqp  = zq + (size_t)gvec*Dn;
    const float* zp = z + (size_t)gvec*Dn;
    float ls = 0.f;
    #pragma unroll
    for (int j = 0; j < 8; j++) {
        int dd = dseg*32 + j*4;
        float4 qv = *reinterpret_cast<const float4*>(&q[dd]);
        float4 rv = *reinterpret_cast<const float4*>(&rsrc[dd]);
        float dx = __fadd_rn(qv.x, -rv.x), dy = __fadd_rn(qv.y, -rv.y);
        float dz = __fadd_rn(qv.z, -rv.z), dw = __fadd_rn(qv.w, -rv.w);
        ls = __fadd_rn(ls, __fmul_rn(dx,dx));
        ls = __fadd_rn(ls, __fmul_rn(dy,dy));
        ls = __fadd_rn(ls, __fmul_rn(dz,dz));
        ls = __fadd_rn(ls, __fmul_rn(dw,dw));
        if (stage != 3) {   // residual never read after stage 3: skip dead store
            float4 nr = make_float4(__fadd_rn(rv.x,-qv.x), __fadd_rn(rv.y,-qv.y),
                                    __fadd_rn(rv.z,-qv.z), __fadd_rn(rv.w,-qv.w));
            *reinterpret_cast<float4*>(&resp[dd]) = nr;
        }
        float4 nz;
        if (stage == 0) {
            nz = qv;                           // 0 + q == q exactly
        } else {
            float4 zv = *reinterpret_cast<const float4*>(&zqp[dd]);
            nz = make_float4(__fadd_rn(zv.x,qv.x), __fadd_rn(zv.y,qv.y),
                             __fadd_rn(zv.z,qv.z), __fadd_rn(zv.w,qv.w));
        }
        if (stage == 3) {                      // straight-through: z + (cum - z)
            float4 zz = *reinterpret_cast<const float4*>(&zp[dd]);
            nz = make_float4(__fadd_rn(zz.x, __fadd_rn(nz.x, -zz.x)),
                             __fadd_rn(zz.y, __fadd_rn(nz.y, -zz.y)),
                             __fadd_rn(zz.z, __fadd_rn(nz.z, -zz.z)),
                             __fadd_rn(zz.w, __fadd_rn(nz.w, -zz.w)));
        }
        *reinterpret_cast<float4*>(&zqp[dd]) = nz;
    }
    #pragma unroll
    for (int o = 2; o; o >>= 1) ls = __fadd_rn(ls, __shfl_down_sync(0xffffffffu, ls, o, 4));
    if (dseg == 0) g_lossv[stage*NVn + gvec] = __fmul_rn(BETA1, ls*(1.f/Dn));
    if (dseg == 1) oidx[(size_t)gvec*NQn + stage] = (float)idx;
}

// ---------------- two-stage loss reduction (deterministic)
__global__ void k_loss1() {
    __shared__ float red[256];
    int t = threadIdx.x, b = blockIdx.x;
    float s = 0.f;
    const float4* p = reinterpret_cast<const float4*>(g_lossv) + b*1000;
    for (int i = t; i < 1000; i += 256) {
        float4 v = p[i];
        s = __fadd_rn(s, v.x); s = __fadd_rn(s, v.y);
        s = __fadd_rn(s, v.z); s = __fadd_rn(s, v.w);
    }
    red[t] = s; __syncthreads();
    for (int o = 128; o; o >>= 1) {
        if (t < o) red[t] = __fadd_rn(red[t], red[t+o]);
        __syncthreads();
    }
    if (t == 0) g_lpart[b] = red[0];
}
__global__ void k_loss2(float* __restrict__ out) {
    if (threadIdx.x == 0) {
        float s = 0.f;
        for (int i = 0; i < 80; i++) s = __fadd_rn(s, g_lpart[i]);
        out[0] = s * (1.f/(float)(NQn*NVn));
    }
}

extern "C" void kernel_launch(void* const* d_in, const int* in_sizes, int n_in,
                              void* d_out, int out_size) {
    const float* z   = (const float*)d_in[0];
    const float* emb = (const float*)d_in[1];
    const float* A   = (const float*)d_in[2];
    const float* W   = (const float*)d_in[3];
    const float* b   = (const float*)d_in[4];
    const float* lns = (const float*)d_in[5];
    const float* lnb = (const float*)d_in[6];
    float* out  = (float*)d_out;
    float* zq   = out;
    float* loss = out + (size_t)NVn*Dn;
    float* oidx = loss + 1;

    const int GCN_SMEM = GCN_FLOATS * 4;   // 226880 B
    cudaFuncSetAttribute(k_gcn,  cudaFuncAttributeMaxDynamicSharedMemorySize, GCN_SMEM);
    cudaFuncSetAttribute(k_pref, cudaFuncAttributeMaxDynamicSharedMemorySize, PF_SMEM);

    k_cnorm<<<512, 256>>>(emb);
    k_wconv<<<2048, 256>>>(emb);
    for (int k = 0; k < NQn; k++) {
        k_gcn<<<BTn/4, 512, GCN_SMEM>>>(A, W, b, lns, lnb, z, k);
        k_pref<<<625, 256, PF_SMEM>>>(k);
        k_update<<<1250, 256>>>(emb, k, z, zq, oidx);
    }
    k_loss1<<<80, 256>>>();
    k_loss2<<<1, 32>>>(loss);
}